// round 16
// baseline (speedup 1.0000x reference)
#include <cuda_runtime.h>
#include <math.h>
#include <stdint.h>

#define NT 4096
#define DD 1024
#define HH 4096
#define NE 8
#define TILE_M 128
#define MAXPAIRS (NT*2 + NE*TILE_M)   // 9216
#define NTILES (MAXPAIRS/TILE_M)      // 72
#define STAGE_Q 32768                  // Ahi 8K | Alo 8K | Bhi 8K | Blo 8K
#define SMEM_Q (4*STAGE_Q)             // 131072

// ---------------- scratch ----------------
__device__ int8_t g_xq_hi[(size_t)NT * DD];
__device__ int8_t g_xq_lo[(size_t)NT * DD];
__device__ float  g_xs[NT];
__device__ float  g_h[(size_t)MAXPAIRS * HH];
__device__ int8_t g_hq_hi[(size_t)MAXPAIRS * HH];
__device__ int8_t g_hq_lo[(size_t)MAXPAIRS * HH];
__device__ float  g_hs[MAXPAIRS];
__device__ float  g_o[(size_t)MAXPAIRS * DD];
__device__ int8_t g_w1q_hi[(size_t)NE * HH * DD];  // [E][N=H][K=D]
__device__ int8_t g_w1q_lo[(size_t)NE * HH * DD];
__device__ float  g_w1s[NE * HH];
__device__ int8_t g_w2q_hi[(size_t)NE * DD * HH];  // [E][N=D][K=H]
__device__ int8_t g_w2q_lo[(size_t)NE * DD * HH];
__device__ float  g_w2s[NE * DD];
__device__ float  g_w2p[4][NE * DD];               // partial col-maxes
__device__ int   g_tok_expert[NT*2];
__device__ float g_tok_gate[NT*2];
__device__ int   g_pair_pos[NT*2];
__device__ int   g_pair_token[MAXPAIRS];
__device__ int   g_offsets[NE+1];
__device__ int   g_tile_expert[NTILES];

// ---------------- asm helpers ----------------
__device__ __forceinline__ uint32_t smem_u32(const void* p) {
    uint32_t a;
    asm("{ .reg .u64 t; cvta.to.shared.u64 t, %1; cvt.u32.u64 %0, t; }" : "=r"(a) : "l"(p));
    return a;
}
#define CPA(dst, src, sz) \
    asm volatile("cp.async.cg.shared.global [%0], [%1], 16, %2;" \
        :: "r"(dst), "l"(src), "r"(sz))
#define CPA_COMMIT() asm volatile("cp.async.commit_group;")
#define CPA_WAIT2()  asm volatile("cp.async.wait_group 2;")
#define CPA_WAIT1()  asm volatile("cp.async.wait_group 1;")
#define CPA_WAIT0()  asm volatile("cp.async.wait_group 0;")
#define LDSM4(r0,r1,r2,r3, a) \
    asm volatile("ldmatrix.sync.aligned.m8n8.x4.shared.b16 {%0,%1,%2,%3}, [%4];" \
        : "=r"(r0), "=r"(r1), "=r"(r2), "=r"(r3) : "r"(a))
#define MMA_S8(c, a0,a1,a2,a3, b0,b1) \
  asm volatile("mma.sync.aligned.m16n8k32.row.col.s32.s8.s8.s32 " \
    "{%0,%1,%2,%3}, {%4,%5,%6,%7}, {%8,%9}, {%0,%1,%2,%3};" \
    : "+r"((c)[0]), "+r"((c)[1]), "+r"((c)[2]), "+r"((c)[3]) \
    : "r"(a0), "r"(a1), "r"(a2), "r"(a3), "r"(b0), "r"(b1))

// quantize 4 floats -> packed hi/lo bytes
__device__ __forceinline__ uint32_t pack_q(float4 v, float inv, uint32_t& lo) {
    uint32_t hi = 0; lo = 0;
    float q, qh, ql;
#define QQ(comp, sh) { q = rintf((comp)*inv); qh = rintf(q*0.0078125f); ql = q - 128.f*qh; \
    hi |= ((uint32_t)(uint8_t)(int8_t)(int)qh) << (sh); \
    lo |= ((uint32_t)(uint8_t)(int8_t)(int)ql) << (sh); }
    QQ(v.x, 0) QQ(v.y, 8) QQ(v.z, 16) QQ(v.w, 24)
#undef QQ
    return hi;
}

// ---------------- gate + x-quant + weight col-max (fused; grid 768) ----------------
__global__ void gate_k(const float* __restrict__ x, const float* __restrict__ wg,
                       const float* __restrict__ W1, const float* __restrict__ W2) {
    if (blockIdx.x >= 512) {
        int bid2 = blockIdx.x - 512;
        if (bid2 < 128) {                       // W1 col-max: max_k |W1[e,k,n]|
            int e = bid2 >> 4, n = (bid2 & 15) * 256 + threadIdx.x;
            const float* p = W1 + (size_t)e * DD * HH + n;
            float m = 0.f;
            for (int k = 0; k < DD; k += 8) {
#pragma unroll
                for (int u = 0; u < 8; u++) m = fmaxf(m, fabsf(p[(size_t)(k + u) * HH]));
            }
            g_w1s[e * HH + n] = fmaxf(m, 1e-30f);
        } else {                                // W2 partial col-max (k-quarter)
            int b3 = bid2 - 128;
            int e = b3 >> 4, ng = (b3 >> 2) & 3, kq = b3 & 3;
            int n = ng * 256 + threadIdx.x;
            const float* p = W2 + (size_t)e * HH * DD + (size_t)kq * 1024 * DD + n;
            float m = 0.f;
            for (int k = 0; k < 1024; k += 8) {
#pragma unroll
                for (int u = 0; u < 8; u++) m = fmaxf(m, fabsf(p[(size_t)(k + u) * DD]));
            }
            g_w2p[kq][e * DD + n] = m;
        }
        return;
    }
    __shared__ float s_wg[DD * NE];
    for (int i = threadIdx.x; i < DD * NE; i += 256) s_wg[i] = wg[i];
    __syncthreads();
    int warp = threadIdx.x >> 5, lane = threadIdx.x & 31;
    int b = blockIdx.x * 8 + warp;
    const float* xr = x + (size_t)b * DD;
    float acc[NE], mx = 0.f;
#pragma unroll
    for (int e = 0; e < NE; e++) acc[e] = 0.f;
    for (int k = lane; k < DD; k += 32) {
        float xv = xr[k];
        mx = fmaxf(mx, fabsf(xv));
        const float* w = &s_wg[k * NE];
#pragma unroll
        for (int e = 0; e < NE; e++) acc[e] += xv * w[e];
    }
#pragma unroll
    for (int e = 0; e < NE; e++) {
#pragma unroll
        for (int o = 16; o; o >>= 1) acc[e] += __shfl_xor_sync(0xffffffffu, acc[e], o);
    }
#pragma unroll
    for (int o = 16; o; o >>= 1) mx = fmaxf(mx, __shfl_xor_sync(0xffffffffu, mx, o));
    mx = fmaxf(mx, 1e-30f);
    if (lane == 0) {
        g_xs[b] = mx;
        int i0 = 0; float l0 = acc[0];
#pragma unroll
        for (int e = 1; e < NE; e++) if (acc[e] > l0) { l0 = acc[e]; i0 = e; }
        int i1 = -1; float l1 = -3.4e38f;
#pragma unroll
        for (int e = 0; e < NE; e++) if (e != i0 && acc[e] > l1) { l1 = acc[e]; i1 = e; }
        float e1  = expf(l1 - l0);
        float inv = 1.f / (1.f + e1);
        g_tok_expert[b*2] = i0;  g_tok_expert[b*2+1] = i1;
        g_tok_gate[b*2]   = inv; g_tok_gate[b*2+1]   = e1 * inv;
    }
    float inv = 16256.f / mx;
#pragma unroll
    for (int j = 0; j < 8; j++) {
        int k = j * 128 + lane * 4;
        float4 v = *(const float4*)(xr + k);
        uint32_t lo, hi = pack_q(v, inv, lo);
        ((uint32_t*)g_xq_hi)[((size_t)b * DD + k) >> 2] = hi;
        ((uint32_t*)g_xq_lo)[((size_t)b * DD + k) >> 2] = lo;
    }
}

// ------- weight transpose + int8 quantize: [E][K][N] f32 -> [E][N][K] int8 hi/lo -------
__global__ __launch_bounds__(256)
void trans_all_k(const float* __restrict__ W1, const float* __restrict__ W2) {
    int bid = blockIdx.x;
    bool w1 = bid < 8192;
    int K, N, e, bx, by;
    const float* in;
    int8_t *ohi, *olo;
    if (w1) {
        K = DD; N = HH;
        e = bid >> 10; int rem = bid & 1023;
        by = rem >> 6; bx = rem & 63;
        in = W1; ohi = g_w1q_hi; olo = g_w1q_lo;
    } else {
        bid -= 8192;
        K = HH; N = DD;
        e = bid >> 10; int rem = bid & 1023;
        by = rem >> 4; bx = rem & 15;
        in = W2; ohi = g_w2q_hi; olo = g_w2q_lo;
    }
    __shared__ float tile[64][65];
    int k0 = by * 64, n0 = bx * 64;
    int t = threadIdx.x;
    {
        int tx = t & 15, ty = t >> 4;
        const float* src = in + ((size_t)e * K + k0) * N + n0;
#pragma unroll
        for (int ii = 0; ii < 4; ii++) {
            float4 v = *(const float4*)(src + (size_t)(ty + ii * 16) * N + tx * 4);
            tile[ty + ii * 16][tx * 4 + 0] = v.x;
            tile[ty + ii * 16][tx * 4 + 1] = v.y;
            tile[ty + ii * 16][tx * 4 + 2] = v.z;
            tile[ty + ii * 16][tx * 4 + 3] = v.w;
        }
    }
    __syncthreads();
    int tx = t & 7, ty = t >> 3;
#pragma unroll
    for (int jj = 0; jj < 2; jj++) {
        int n = ty + jj * 32;
        int nn = n0 + n;
        float m;
        if (w1) m = g_w1s[e * HH + nn];
        else {
            m = fmaxf(fmaxf(g_w2p[0][e * DD + nn], g_w2p[1][e * DD + nn]),
                      fmaxf(g_w2p[2][e * DD + nn], g_w2p[3][e * DD + nn]));
            m = fmaxf(m, 1e-30f);
            g_w2s[e * DD + nn] = m;       // redundant across k0-blocks; same value
        }
        float inv = 16256.f / m;
        float4 v0 = make_float4(tile[tx*8+0][n], tile[tx*8+1][n], tile[tx*8+2][n], tile[tx*8+3][n]);
        float4 v1 = make_float4(tile[tx*8+4][n], tile[tx*8+5][n], tile[tx*8+6][n], tile[tx*8+7][n]);
        uint32_t lo0, lo1;
        uint32_t hi0 = pack_q(v0, inv, lo0);
        uint32_t hi1 = pack_q(v1, inv, lo1);
        size_t ob = ((size_t)e * N + nn) * K + k0 + tx * 8;
        *(uint2*)(ohi + ob) = make_uint2(hi0, hi1);
        *(uint2*)(olo + ob) = make_uint2(lo0, lo1);
    }
}

// ------- offsets + scatter -------
__global__ void offsets_scatter_k() {
    __shared__ int s_cnt[NE];
    __shared__ int s_cur[NE];
    int t = threadIdx.x;
    for (int i = t; i < MAXPAIRS; i += 256) g_pair_token[i] = -1;
    if (t < NE) s_cnt[t] = 0;
    __syncthreads();
    for (int i = t; i < NT * 2; i += 256)
        atomicAdd(&s_cnt[g_tok_expert[i]], 1);
    __syncthreads();
    if (t == 0) {
        int off = 0;
        for (int e = 0; e < NE; e++) {
            g_offsets[e] = off;
            s_cur[e] = off;
            int ct = (s_cnt[e] + TILE_M - 1) / TILE_M;
            for (int it = 0; it < ct; it++) g_tile_expert[off / TILE_M + it] = e;
            off += ct * TILE_M;
        }
        g_offsets[NE] = off;
        for (int it = off / TILE_M; it < NTILES; it++) g_tile_expert[it] = -1;
    }
    __syncthreads();
    for (int i = t; i < NT * 2; i += 256) {
        int e = g_tok_expert[i];
        int p = atomicAdd(&s_cur[e], 1);
        g_pair_token[p] = i >> 1;
        g_pair_pos[i] = p;
    }
}

// ---------------- int8 2-slice grouped GEMM, tile 128x128, KC=64 ----------------
// stage (32KB): Ahi[128][64B] @0 | Alo @8192 | Bhi @16384 | Blo @24576
// 16B-slot swizzle: byte = row*64 + ((c ^ ((row>>1)&3))<<4)
template<bool FIRST>
__global__ __launch_bounds__(256, 1)
void gemm_q(const float* __restrict__ bias_g) {
    constexpr int KTOT = FIRST ? DD : HH;
    constexpr int NTOT = FIRST ? HH : DD;
    constexpr int NC = KTOT / 64;
    int mt = blockIdx.y;
    int e = g_tile_expert[mt];
    if (e < 0) return;
    extern __shared__ char sm[];
    uint32_t sb = smem_u32(sm);
    int tid = threadIdx.x, lane = tid & 31, w = tid >> 5;
    int wr = w >> 2, wc = w & 3;                 // warp grid 2x4, warp tile 64x32
    int m0 = mt * TILE_M, n0 = blockIdx.x * 128;

    // loaders: rows r0, r0+64; 16B slot lc
    int r0 = tid >> 2, lc = tid & 3;
    int r1 = r0 + 64;
    uint32_t d0 = (uint32_t)(r0 * 64 + ((lc ^ ((r0 >> 1) & 3)) << 4));
    uint32_t d1 = (uint32_t)(r1 * 64 + ((lc ^ ((r1 >> 1) & 3)) << 4));
    const char *pA0, *pA1, *pB0, *pB1;
    uint32_t szA0 = 16, szA1 = 16;
    long long dAlo, dBlo;
    if (FIRST) {
        int t0 = g_pair_token[m0 + r0], t1 = g_pair_token[m0 + r1];
        pA0 = (const char*)g_xq_hi + (size_t)(t0 < 0 ? 0 : t0) * DD + lc * 16;
        pA1 = (const char*)g_xq_hi + (size_t)(t1 < 0 ? 0 : t1) * DD + lc * 16;
        if (t0 < 0) szA0 = 0;
        if (t1 < 0) szA1 = 0;
        dAlo = (const char*)g_xq_lo - (const char*)g_xq_hi;
        pB0 = (const char*)g_w1q_hi + ((size_t)e * NTOT + n0 + r0) * KTOT + lc * 16;
        pB1 = (const char*)g_w1q_hi + ((size_t)e * NTOT + n0 + r1) * KTOT + lc * 16;
        dBlo = (const char*)g_w1q_lo - (const char*)g_w1q_hi;
    } else {
        pA0 = (const char*)g_hq_hi + (size_t)(m0 + r0) * HH + lc * 16;
        pA1 = (const char*)g_hq_hi + (size_t)(m0 + r1) * HH + lc * 16;
        dAlo = (const char*)g_hq_lo - (const char*)g_hq_hi;
        pB0 = (const char*)g_w2q_hi + ((size_t)e * NTOT + n0 + r0) * KTOT + lc * 16;
        pB1 = (const char*)g_w2q_hi + ((size_t)e * NTOT + n0 + r1) * KTOT + lc * 16;
        dBlo = (const char*)g_w2q_lo - (const char*)g_w2q_hi;
    }

    // ldmatrix offsets: rows (lane&7)+((lane>>3)&1)*8, slot kk*2+(lane>>4)
    int rA = wr * 64 + (lane & 7) + ((lane >> 3) & 1) * 8;
    int rB = wc * 32 + (lane & 7) + ((lane >> 3) & 1) * 8;
    uint32_t offA[2], offB[2];
#pragma unroll
    for (int kk = 0; kk < 2; kk++) {
        int sA = kk * 2 + (lane >> 4);
        offA[kk] = (uint32_t)(rA * 64 + ((sA ^ ((rA >> 1) & 3)) << 4));
        offB[kk] = (uint32_t)(rB * 64 + ((sA ^ ((rB >> 1) & 3)) << 4));
    }

    int acc1[4][4][4], acc2[4][4][4];
#pragma unroll
    for (int i = 0; i < 4; i++)
#pragma unroll
        for (int j = 0; j < 4; j++)
#pragma unroll
            for (int q = 0; q < 4; q++) { acc1[i][j][q] = 0; acc2[i][j][q] = 0; }

    auto LOAD = [&](int ch) {
        uint32_t st = sb + (uint32_t)(ch & 3) * STAGE_Q;
        long long ko = (long long)ch * 64;
        CPA(st + d0,          pA0 + ko,        szA0);
        CPA(st + d1,          pA1 + ko,        szA1);
        CPA(st + 8192 + d0,   pA0 + dAlo + ko, szA0);
        CPA(st + 8192 + d1,   pA1 + dAlo + ko, szA1);
        CPA(st + 16384 + d0,  pB0 + ko,        16u);
        CPA(st + 16384 + d1,  pB1 + ko,        16u);
        CPA(st + 24576 + d0,  pB0 + dBlo + ko, 16u);
        CPA(st + 24576 + d1,  pB1 + dBlo + ko, 16u);
        CPA_COMMIT();
    };

    LOAD(0); LOAD(1); LOAD(2);
    for (int ch = 0; ch < NC; ch++) {
        if (ch < NC - 2) { CPA_WAIT2(); }
        else if (ch == NC - 2) { CPA_WAIT1(); }
        else { CPA_WAIT0(); }
        __syncthreads();
        if (ch + 3 < NC) LOAD(ch + 3);
        uint32_t st = sb + (uint32_t)(ch & 3) * STAGE_Q;
#pragma unroll
        for (int kk = 0; kk < 2; kk++) {       // two k32 halves of the 64B row
            uint32_t bh[8], bl[8];
            LDSM4(bh[0], bh[1], bh[2], bh[3], st + 16384 + offB[kk]);           // n-octets 0,1
            LDSM4(bh[4], bh[5], bh[6], bh[7], st + 16384 + offB[kk] + 1024u);   // n-octets 2,3
            LDSM4(bl[0], bl[1], bl[2], bl[3], st + 24576 + offB[kk]);
            LDSM4(bl[4], bl[5], bl[6], bl[7], st + 24576 + offB[kk] + 1024u);
#pragma unroll
            for (int i = 0; i < 4; i++) {
                uint32_t ah[4], al[4];
                LDSM4(ah[0], ah[1], ah[2], ah[3], st + offA[kk] + (uint32_t)i * 1024u);
                LDSM4(al[0], al[1], al[2], al[3], st + 8192 + offA[kk] + (uint32_t)i * 1024u);
#pragma unroll
                for (int j = 0; j < 4; j++) {
                    int b0i = (j >> 1) * 4 + (j & 1), b1i = b0i + 2;
                    MMA_S8(acc1[i][j], ah[0], ah[1], ah[2], ah[3], bh[b0i], bh[b1i]);
                    MMA_S8(acc2[i][j], ah[0], ah[1], ah[2], ah[3], bl[b0i], bl[b1i]);
                    MMA_S8(acc2[i][j], al[0], al[1], al[2], al[3], bh[b0i], bh[b1i]);
                }
            }
        }
    }

    // epilogue: o = sA*sB*(16384*acc1 + 128*acc2) + bias
    int g = lane >> 2, tg = lane & 3;
    const float* ws = (FIRST ? g_w1s : g_w2s) + (size_t)e * NTOT + n0;
    const float* bias = bias_g + (size_t)e * NTOT + n0;
    const float SCL = 1.f / (16256.f * 16256.f);
#pragma unroll
    for (int i = 0; i < 4; i++) {
        int row = m0 + wr * 64 + i * 16 + g;
        float sa0, sa1;
        if (FIRST) {
            int t0 = g_pair_token[row], t1 = g_pair_token[row + 8];
            sa0 = g_xs[t0 < 0 ? 0 : t0];
            sa1 = g_xs[t1 < 0 ? 0 : t1];
        } else {
            sa0 = g_hs[row]; sa1 = g_hs[row + 8];
        }
        sa0 *= SCL; sa1 *= SCL;
#pragma unroll
        for (int j = 0; j < 4; j++) {
            int nc = wc * 32 + j * 8 + tg * 2;
            float sb0 = ws[nc], sb1 = ws[nc + 1];
            float b0v = bias[nc], b1v = bias[nc + 1];
            float v0 = sa0 * sb0 * (16384.f * (float)acc1[i][j][0] + 128.f * (float)acc2[i][j][0]) + b0v;
            float v1 = sa0 * sb1 * (16384.f * (float)acc1[i][j][1] + 128.f * (float)acc2[i][j][1]) + b1v;
            float v2 = sa1 * sb0 * (16384.f * (float)acc1[i][j][2] + 128.f * (float)acc2[i][j][2]) + b0v;
            float v3 = sa1 * sb1 * (16384.f * (float)acc1[i][j][3] + 128.f * (float)acc2[i][j][3]) + b1v;
            if (FIRST) {
                v0 = fmaxf(v0, 0.f); v1 = fmaxf(v1, 0.f);
                v2 = fmaxf(v2, 0.f); v3 = fmaxf(v3, 0.f);
                float2 p0 = make_float2(v0, v1), p1 = make_float2(v2, v3);
                *(float2*)(g_h + (size_t)row * HH + n0 + nc)       = p0;
                *(float2*)(g_h + (size_t)(row + 8) * HH + n0 + nc) = p1;
            } else {
                *(float2*)(g_o + (size_t)row * DD + n0 + nc)       = make_float2(v0, v1);
                *(float2*)(g_o + (size_t)(row + 8) * DD + n0 + nc) = make_float2(v2, v3);
            }
        }
    }
}

// ---------------- h row quantize ----------------
__global__ __launch_bounds__(256)
void hquant_k() {
    int row = blockIdx.x;
    int tid = threadIdx.x;
    const float4* hr = (const float4*)(g_h + (size_t)row * HH);
    float4 v[4];
    float m = 0.f;
#pragma unroll
    for (int u = 0; u < 4; u++) {
        v[u] = hr[tid * 4 + u];
        m = fmaxf(m, fmaxf(fmaxf(fabsf(v[u].x), fabsf(v[u].y)),
                           fmaxf(fabsf(v[u].z), fabsf(v[u].w))));
    }
    __shared__ float red[256];
    red[tid] = m;
    __syncthreads();
    for (int s = 128; s; s >>= 1) {
        if (tid < s) red[tid] = fmaxf(red[tid], red[tid + s]);
        __syncthreads();
    }
    float mx = fmaxf(red[0], 1e-30f);
    if (tid == 0) g_hs[row] = mx;
    float inv = 16256.f / mx;
    uint32_t hi[4], lo[4];
#pragma unroll
    for (int u = 0; u < 4; u++) hi[u] = pack_q(v[u], inv, lo[u]);
    ((uint4*)(g_hq_hi + (size_t)row * HH))[tid] = make_uint4(hi[0], hi[1], hi[2], hi[3]);
    ((uint4*)(g_hq_lo + (size_t)row * HH))[tid] = make_uint4(lo[0], lo[1], lo[2], lo[3]);
}

// ---------------- combine ----------------
__global__ void combine_k(float* __restrict__ y) {
    int idx = blockIdx.x * 256 + threadIdx.x;
    int b = idx >> 10;
    int d = idx & 1023;
    int p0 = g_pair_pos[b*2], p1 = g_pair_pos[b*2+1];
    float g0 = g_tok_gate[b*2], g1 = g_tok_gate[b*2+1];
    float o0 = g_o[(size_t)p0 * DD + d];
    float o1 = g_o[(size_t)p1 * DD + d];
    float om = fmaxf(o0, o1), on = fminf(o0, o1);
    float gm = (o0 >= o1) ? g0 : g1;
    float gn = (o0 >= o1) ? g1 : g0;
    y[idx] = om + __logf(fmaf(gn, __expf(on - om), gm));
}

// ---------------- balancing loss ----------------
__global__ void loss_k(const float* __restrict__ loss_coef, float* __restrict__ out,
                       int out_size) {
    __shared__ float s_imp[256 * NE];
    __shared__ float s_cnt[256 * NE];
    int t = threadIdx.x;
    float imp[NE], cnt[NE];
#pragma unroll
    for (int e = 0; e < NE; e++) { imp[e] = 0.f; cnt[e] = 0.f; }
    for (int b = t; b < NT; b += 256) {
#pragma unroll
        for (int s = 0; s < 2; s++) {
            int e = g_tok_expert[b*2+s];
            imp[e] += g_tok_gate[b*2+s];
            cnt[e] += 1.f;
        }
    }
#pragma unroll
    for (int e = 0; e < NE; e++) { s_imp[t*NE+e] = imp[e]; s_cnt[t*NE+e] = cnt[e]; }
    __syncthreads();
    for (int stride = 128; stride; stride >>= 1) {
        if (t < stride) {
#pragma unroll
            for (int e = 0; e < NE; e++) {
                s_imp[t*NE+e] += s_imp[(t+stride)*NE+e];
                s_cnt[t*NE+e] += s_cnt[(t+stride)*NE+e];
            }
        }
        __syncthreads();
    }
    if (t == 0) {
        float cv2[2];
        for (int which = 0; which < 2; which++) {
            const float* v = which == 0 ? s_imp : s_cnt;
            float mean = 0.f;
            for (int e = 0; e < NE; e++) mean += v[e];
            mean /= (float)NE;
            float var = 0.f;
            for (int e = 0; e < NE; e++) { float d = v[e] - mean; var += d * d; }
            var /= (float)(NE - 1);
            cv2[which] = var / (mean * mean + 1e-10f);
        }
        float loss = (cv2[0] + cv2[1]) * loss_coef[0];
        if (out_size > NT * DD) out[NT * DD] = loss;
    }
}

// ---------------- launch ----------------
extern "C" void kernel_launch(void* const* d_in, const int* in_sizes, int n_in,
                              void* d_out, int out_size) {
    const float* x  = (const float*)d_in[0];
    const float* wg = (const float*)d_in[1];
    const float* W1 = (const float*)d_in[2];
    const float* b1 = (const float*)d_in[3];
    const float* W2 = (const float*)d_in[4];
    const float* b2 = (const float*)d_in[5];
    const float* lc = (const float*)d_in[6];
    float* out = (float*)d_out;

    cudaFuncSetAttribute(gemm_q<true>,  cudaFuncAttributeMaxDynamicSharedMemorySize, SMEM_Q);
    cudaFuncSetAttribute(gemm_q<false>, cudaFuncAttributeMaxDynamicSharedMemorySize, SMEM_Q);

    gate_k<<<768, 256>>>(x, wg, W1, W2);                 // #1 gate + xquant + wmax
    trans_all_k<<<16384, 256>>>(W1, W2);                 // #2 transpose + int8 quantize
    offsets_scatter_k<<<1, 256>>>();                     // #3
    gemm_q<true ><<<dim3(HH/128, NTILES), 256, SMEM_Q>>>(b1);   // #4 <- ncu slot
    hquant_k<<<MAXPAIRS, 256>>>();                       // #5
    gemm_q<false><<<dim3(DD/128, NTILES), 256, SMEM_Q>>>(b2);   // #6
    combine_k<<<(NT * DD) / 256, 256>>>(out);            // #7
    loss_k<<<1, 256>>>(lc, out, out_size);               // #8
}